// round 3
// baseline (speedup 1.0000x reference)
#include <cuda_runtime.h>

#define D       64
#define DV      16          // D/4 float4 per row
#define MAX_N   100000

// Scratch: Y = X @ W^T, [N, 64] as float4[N*16]. __device__ global (no alloc allowed).
__device__ float4 g_Y[MAX_N * DV];

// ---------------------------------------------------------------------------
// Kernel 1: Y[n] = X[n] @ W^T ; out[n] = bias
// One node per thread. W (16KB) staged in smem, X row held in 16 float4 regs.
// ---------------------------------------------------------------------------
__global__ __launch_bounds__(256) void xform_init_kernel(
    const float4* __restrict__ X,      // [N*16]
    const float4* __restrict__ W,      // [64*16]  (row o = W[o*16 .. o*16+15])
    const float4* __restrict__ bias,   // [16]
    float4* __restrict__ out,          // [N*16]
    int N)
{
    __shared__ float4 Ws[D * DV];
    __shared__ float4 bsh[DV];

    for (int i = threadIdx.x; i < D * DV; i += blockDim.x)
        Ws[i] = W[i];
    if (threadIdx.x < DV)
        bsh[threadIdx.x] = bias[threadIdx.x];
    __syncthreads();

    int n = blockIdx.x * blockDim.x + threadIdx.x;
    if (n >= N) return;

    float4 x[DV];
#pragma unroll
    for (int i = 0; i < DV; i++) x[i] = X[n * DV + i];

#pragma unroll
    for (int og = 0; og < DV; og++) {
        float a0 = 0.f, a1 = 0.f, a2 = 0.f, a3 = 0.f;
#pragma unroll
        for (int i = 0; i < DV; i++) {
            float4 xi = x[i];
            float4 w0 = Ws[(og * 4 + 0) * DV + i];
            float4 w1 = Ws[(og * 4 + 1) * DV + i];
            float4 w2 = Ws[(og * 4 + 2) * DV + i];
            float4 w3 = Ws[(og * 4 + 3) * DV + i];
            a0 += xi.x * w0.x + xi.y * w0.y + xi.z * w0.z + xi.w * w0.w;
            a1 += xi.x * w1.x + xi.y * w1.y + xi.z * w1.z + xi.w * w1.w;
            a2 += xi.x * w2.x + xi.y * w2.y + xi.z * w2.z + xi.w * w2.w;
            a3 += xi.x * w3.x + xi.y * w3.y + xi.z * w3.z + xi.w * w3.w;
        }
        g_Y[n * DV + og] = make_float4(a0, a1, a2, a3);
        out[n * DV + og] = bsh[og];   // bias init (also handles zero-degree nodes)
    }
}

// ---------------------------------------------------------------------------
// Kernel 2: out[row[e]] += vals[e] * Y[col[e]]
// 16 threads per edge; thread q handles float4 chunk q. The 16 lanes of an
// edge touch 256 contiguous bytes of Y and of out -> 2 L2 lines each.
// Vector red.global.add.v4.f32 (sm_90+) = 1 REDG per 16B.
// ---------------------------------------------------------------------------
__device__ __forceinline__ void red_add_v4(float4* addr, float4 v) {
    asm volatile("red.global.add.v4.f32 [%0], {%1, %2, %3, %4};"
                 :: "l"(addr), "f"(v.x), "f"(v.y), "f"(v.z), "f"(v.w)
                 : "memory");
}

__global__ __launch_bounds__(256) void edge_scatter_kernel(
    const int*   __restrict__ row,
    const int*   __restrict__ col,
    const float* __restrict__ vals,
    float4*      __restrict__ out,
    int E)
{
    unsigned int t = blockIdx.x * blockDim.x + threadIdx.x;
    int e = (int)(t >> 4);
    int q = (int)(t & 15);
    if (e >= E) return;

    int   r = __ldg(row  + e);
    int   c = __ldg(col  + e);
    float v = __ldg(vals + e);

    float4 y = g_Y[c * DV + q];
    float4 m = make_float4(v * y.x, v * y.y, v * y.z, v * y.w);
    red_add_v4(out + (size_t)r * DV + q, m);
}

// ---------------------------------------------------------------------------
// Launch: inputs in metadata order: row, col, vals, X, weight, bias
// ---------------------------------------------------------------------------
extern "C" void kernel_launch(void* const* d_in, const int* in_sizes, int n_in,
                              void* d_out, int out_size)
{
    const int*   row  = (const int*)  d_in[0];
    const int*   col  = (const int*)  d_in[1];
    const float* vals = (const float*)d_in[2];
    const float* X    = (const float*)d_in[3];
    const float* W    = (const float*)d_in[4];
    const float* bias = (const float*)d_in[5];
    float*       out  = (float*)d_out;

    int E = in_sizes[0];
    int N = in_sizes[3] / D;   // 100000

    xform_init_kernel<<<(N + 255) / 256, 256>>>(
        (const float4*)X, (const float4*)W, (const float4*)bias,
        (float4*)out, N);

    unsigned int total = (unsigned int)E * 16u;
    edge_scatter_kernel<<<(total + 255u) / 256u, 256>>>(
        row, col, vals, (float4*)out, E);
}

// round 4
// speedup vs baseline: 1.2677x; 1.2677x over previous
#include <cuda_runtime.h>

#define D       64
#define DV      16          // D/4 float4 per row
#define MAX_N   100000
#define EPT     4           // edges per thread in scatter kernel

// Scratch: Y = X @ W^T, [N, 64] as float4[N*16]. __device__ global (no alloc allowed).
__device__ float4 g_Y[MAX_N * DV];

// ---------------------------------------------------------------------------
// Kernel 1: register-tiled GEMM  Y = X @ W^T ; out = bias
// Block tile: 64 nodes x 64 outs (full), K=64. 256 threads, 4x4 micro-tile.
// Xs and Ws stored k-major (transposed) so fragments are LDS.128.
// ---------------------------------------------------------------------------
#define TPAD 68   // row stride in floats (272B, 16B-aligned)

__global__ __launch_bounds__(256) void xform_init_kernel(
    const float*  __restrict__ X,      // [N, 64]
    const float*  __restrict__ W,      // [64, 64] (row o)
    const float4* __restrict__ bias,   // [16]
    float4*       __restrict__ out,    // [N*16]
    int N)
{
    __shared__ float Xs[D * TPAD];   // Xs[k][m]
    __shared__ float Ws[D * TPAD];   // Ws[k][o]

    const int tid = threadIdx.x;
    const int node0 = blockIdx.x * 64;

    // Stage X tile and W, transposed into smem. 256 threads, float4 loads.
    // Each pass: 16 rows x 16 float4-cols. 4 passes cover 64 rows.
    {
        int r  = tid >> 4;          // 0..15
        int cv = tid & 15;          // float4 column 0..15
#pragma unroll
        for (int p = 0; p < 4; p++) {
            int row = r + p * 16;
            // W tile (always full)
            float4 w = *(const float4*)(W + row * D + cv * 4);
            Ws[(cv * 4 + 0) * TPAD + row] = w.x;
            Ws[(cv * 4 + 1) * TPAD + row] = w.y;
            Ws[(cv * 4 + 2) * TPAD + row] = w.z;
            Ws[(cv * 4 + 3) * TPAD + row] = w.w;
            // X tile (guard tail block)
            int n = node0 + row;
            float4 x = (n < N) ? *(const float4*)(X + (size_t)n * D + cv * 4)
                               : make_float4(0.f, 0.f, 0.f, 0.f);
            Xs[(cv * 4 + 0) * TPAD + row] = x.x;
            Xs[(cv * 4 + 1) * TPAD + row] = x.y;
            Xs[(cv * 4 + 2) * TPAD + row] = x.z;
            Xs[(cv * 4 + 3) * TPAD + row] = x.w;
        }
    }
    __syncthreads();

    // 16x16 thread grid: ty picks node group, tx picks output group
    const int tx = tid & 15;        // out cols n = tx*4 .. tx*4+3
    const int ty = tid >> 4;        // nodes    m = ty*4 .. ty*4+3
    const int m4 = ty * 4;
    const int n4 = tx * 4;

    float acc[4][4];
#pragma unroll
    for (int i = 0; i < 4; i++)
#pragma unroll
        for (int j = 0; j < 4; j++) acc[i][j] = 0.f;

#pragma unroll 8
    for (int k = 0; k < D; k++) {
        float4 xf = *(const float4*)(Xs + k * TPAD + m4);
        float4 wf = *(const float4*)(Ws + k * TPAD + n4);
        const float xv[4] = {xf.x, xf.y, xf.z, xf.w};
        const float wv[4] = {wf.x, wf.y, wf.z, wf.w};
#pragma unroll
        for (int i = 0; i < 4; i++)
#pragma unroll
            for (int j = 0; j < 4; j++)
                acc[i][j] += xv[i] * wv[j];
    }

    float4 b = bias[tx];
#pragma unroll
    for (int i = 0; i < 4; i++) {
        int n = node0 + m4 + i;
        if (n < N) {
            size_t o = (size_t)n * DV + tx;
            g_Y[o] = make_float4(acc[i][0], acc[i][1], acc[i][2], acc[i][3]);
            out[o] = b;   // bias init (also covers zero-degree nodes)
        }
    }
}

// ---------------------------------------------------------------------------
// Kernel 2: out[row[e]] += vals[e] * Y[col[e]]
// 16 threads per edge-chunk q; each thread handles EPT=4 edges with
// front-batched gathers (MLP=4). RED.v4 is fire-and-forget.
// ---------------------------------------------------------------------------
__device__ __forceinline__ void red_add_v4(float4* addr, float4 v) {
    asm volatile("red.global.add.v4.f32 [%0], {%1, %2, %3, %4};"
                 :: "l"(addr), "f"(v.x), "f"(v.y), "f"(v.z), "f"(v.w)
                 : "memory");
}

__global__ __launch_bounds__(256) void edge_scatter_kernel(
    const int*   __restrict__ row,
    const int*   __restrict__ col,
    const float* __restrict__ vals,
    float4*      __restrict__ out,
    int E)
{
    unsigned int t = blockIdx.x * blockDim.x + threadIdx.x;
    int q  = (int)(t & 15);
    int e0 = (int)(t >> 4) * EPT;
    if (e0 >= E) return;

    if (e0 + EPT <= E) {
        int c[EPT];
#pragma unroll
        for (int j = 0; j < EPT; j++) c[j] = __ldg(col + e0 + j);

        float4 y[EPT];
#pragma unroll
        for (int j = 0; j < EPT; j++) y[j] = __ldg(&g_Y[(size_t)c[j] * DV + q]);

        int   r[EPT];
        float v[EPT];
#pragma unroll
        for (int j = 0; j < EPT; j++) { r[j] = __ldg(row + e0 + j); v[j] = __ldg(vals + e0 + j); }

#pragma unroll
        for (int j = 0; j < EPT; j++) {
            float4 m = make_float4(v[j]*y[j].x, v[j]*y[j].y, v[j]*y[j].z, v[j]*y[j].w);
            red_add_v4(out + (size_t)r[j] * DV + q, m);
        }
    } else {
        for (int e = e0; e < E; e++) {
            int   c = __ldg(col + e);
            int   r = __ldg(row + e);
            float v = __ldg(vals + e);
            float4 y = __ldg(&g_Y[(size_t)c * DV + q]);
            float4 m = make_float4(v*y.x, v*y.y, v*y.z, v*y.w);
            red_add_v4(out + (size_t)r * DV + q, m);
        }
    }
}

// ---------------------------------------------------------------------------
// Launch: inputs in metadata order: row, col, vals, X, weight, bias
// ---------------------------------------------------------------------------
extern "C" void kernel_launch(void* const* d_in, const int* in_sizes, int n_in,
                              void* d_out, int out_size)
{
    const int*   row  = (const int*)  d_in[0];
    const int*   col  = (const int*)  d_in[1];
    const float* vals = (const float*)d_in[2];
    const float* X    = (const float*)d_in[3];
    const float* W    = (const float*)d_in[4];
    const float* bias = (const float*)d_in[5];
    float*       out  = (float*)d_out;

    int E = in_sizes[0];
    int N = in_sizes[3] / D;   // 100000

    xform_init_kernel<<<(N + 63) / 64, 256>>>(
        X, W, (const float4*)bias, (float4*)out, N);

    long long chunks = ((long long)E + EPT - 1) / EPT;   // edge groups
    long long total  = chunks * 16;                       // threads
    int blocks = (int)((total + 255) / 256);
    edge_scatter_kernel<<<blocks, 256>>>(
        row, col, vals, (float4*)out, E);
}